// round 6
// baseline (speedup 1.0000x reference)
#include <cuda_runtime.h>
#include <math.h>

#define HH 2048
#define WW 2048
#define NF 64
#define MAXD 12
#define NSLOT 8191            // heap-ordered tree, depths 0..12
#define PXW 32                // patch width  (warp x-span)
#define PXH 8                 // patch height (rows per thread)
#define NPX (WW / PXW)        // 64
#define NPY (HH / PXH)        // 256

// Explicit tree, heap order. Node j:
//   bit31=1 -> leaf; low 6 bits = frame color index
//   bit31=0 -> interior; bit30 = axis (1=vertical/x), low 16 bits = absolute split coord
__device__ int  g_tree[NSLOT];
__device__ int2 g_pre[NPX * NPY];   // per 32x8 patch: (prefix node, prefix y-reach)

// ---------------------------------------------------------------------------
// Kernel 1: build explicit tree. Thread j walks root -> heap slot j.
// Argmax phase is latency-flat: 4 threads per (frame,side) row, each loads
// its 16 logits into registers (MLP=16), local first-max argmax, 2-shfl merge.
// ---------------------------------------------------------------------------
__global__ __launch_bounds__(512) void k_tree(
    const float* __restrict__ sel,
    const float* __restrict__ ratios)
{
    __shared__ float s_ratio[NF];
    __shared__ int   s_left[NF], s_right[NF];

    const int tid = threadIdx.x;

    // ---- argmax: row = tid>>2 in 0..127, sub = tid&3 covers 16 elements ----
    {
        const int row   = tid >> 2;             // (frame<<1)|side
        const int sub   = tid & 3;
        const int frame = row >> 1;
        const int side  = row & 1;
        const float* p  = sel + frame * 2 * NF + side * NF + sub * 16;

        float vals[16];
        #pragma unroll
        for (int k = 0; k < 16; k++) vals[k] = p[k];   // 16 parallel LDGs

        float best = vals[0];
        int   bi   = sub * 16;
        #pragma unroll
        for (int k = 1; k < 16; k++)
            if (vals[k] > best) { best = vals[k]; bi = sub * 16 + k; }

        #pragma unroll
        for (int off = 1; off <= 2; off <<= 1) {
            float ov = __shfl_xor_sync(0xffffffffu, best, off);
            int   oi = __shfl_xor_sync(0xffffffffu, bi,   off);
            if (ov > best || (ov == best && oi < bi)) { best = ov; bi = oi; }
        }
        if (sub == 0) { if (side == 0) s_left[frame] = bi; else s_right[frame] = bi; }
    }
    if (tid < NF) s_ratio[tid] = ratios[tid];
    __syncthreads();

    const int j = blockIdx.x * 512 + tid;
    if (j >= NSLOT) return;

    const int depth = 31 - __clz(j + 1);        // 0..12
    int idx = 0, x0 = 0, y0 = 0, w = WW, h = HH;

    for (int k = depth - 1; k >= 0; k--) {
        if (w < 2 || h < 2) return;             // ancestor is a leaf -> unreachable slot
        int bit = ((j + 1) >> k) & 1;
        float rt = s_ratio[idx];
        if (idx & 1) {                          // vertical split
            int lw = max(1, (int)floorf((float)w * rt));
            if (bit) { x0 += lw; w -= lw; idx = s_right[idx]; }
            else     { w = lw;            idx = s_left[idx];  }
        } else {                                // horizontal split
            int th = max(1, (int)floorf((float)h * rt));
            if (bit) { y0 += th; h -= th; idx = s_right[idx]; }
            else     { h = th;            idx = s_left[idx];  }
        }
    }

    if (depth == MAXD || w < 2 || h < 2) {
        g_tree[j] = (int)0x80000000 | idx;
    } else {
        float rt = s_ratio[idx];
        if (idx & 1) g_tree[j] = (1 << 30) | (x0 + max(1, (int)floorf((float)w * rt)));
        else         g_tree[j] =             (y0 + max(1, (int)floorf((float)h * rt)));
    }
}

// ---------------------------------------------------------------------------
// Kernel 2: per-patch prefix. Each thread descends root -> its 32x8 patch
// until the split line crosses the patch (or a leaf), recording the running
// y upper bound (min of left-taken horizontal splits).
// ---------------------------------------------------------------------------
__global__ __launch_bounds__(256) void k_pre()
{
    const int id = blockIdx.x * 256 + threadIdx.x;     // 0..16383
    const int px = id & (NPX - 1);
    const int py = id >> 6;
    const int x0 = px * PXW, y0 = py * PXH;

    int cur = 0, reach = HH;
    int v = __ldg(&g_tree[0]);
    while (v >= 0) {
        int s = v & 0xFFFF;
        if (v & (1 << 30)) {                           // vertical split
            if      (x0 + PXW <= s) cur = 2 * cur + 1;
            else if (x0 >= s)       cur = 2 * cur + 2;
            else break;
        } else {                                       // horizontal split
            if      (y0 + PXH <= s) { reach = min(reach, s); cur = 2 * cur + 1; }
            else if (y0 >= s)         cur = 2 * cur + 2;
            else break;
        }
        v = __ldg(&g_tree[cur]);
    }
    g_pre[id] = make_int2(cur, reach);
}

// ---------------------------------------------------------------------------
// Kernel 3: render. Warp = one 32x8 patch; thread owns 8 rows at fixed x.
// y-run reuse: leaf valid while y < reachy; horizontal boundaries hit many
// lanes at the same q -> convergent re-descents. Stores coalesced (128B/warp).
// ---------------------------------------------------------------------------
__global__ __launch_bounds__(256) void k_render(
    const float* __restrict__ colors,
    float* __restrict__ out)
{
    __shared__ float4 s_col[NF];
    const int t = threadIdx.y * 32 + threadIdx.x;
    if (t < NF)
        s_col[t] = make_float4(colors[3 * t], colors[3 * t + 1], colors[3 * t + 2], 0.f);
    __syncthreads();

    const int px    = blockIdx.x;                       // 0..63
    const int py    = blockIdx.y * 8 + threadIdx.y;     // 0..255
    const int x     = px * PXW + threadIdx.x;
    const int ybase = py * PXH;

    const int2 pre = __ldg(&g_pre[py * NPX + px]);

    float4 col = make_float4(0.f, 0.f, 0.f, 0.f);
    int reachy = -1;
    const int base = ybase * WW + x;

    #pragma unroll
    for (int q = 0; q < PXH; q++) {
        const int y = ybase + q;
        if (y >= reachy) {
            int cur = pre.x, ry = pre.y;
            int v = __ldg(&g_tree[cur]);
            while (v >= 0) {
                int s = v & 0xFFFF;
                bool vert = (v & (1 << 30)) != 0;
                int coord = vert ? x : y;
                if (coord >= s) cur = 2 * cur + 2;
                else { if (!vert) ry = min(ry, s); cur = 2 * cur + 1; }
                v = __ldg(&g_tree[cur]);
            }
            col = s_col[v & 63];
            reachy = ry;
        }
        out[base + q * WW]               = col.x;
        out[HH * WW + base + q * WW]     = col.y;
        out[2 * HH * WW + base + q * WW] = col.z;
    }
}

extern "C" void kernel_launch(void* const* d_in, const int* in_sizes, int n_in,
                              void* d_out, int out_size) {
    const float* colors = (const float*)d_in[0];   // frame_colors    [64, 3]
    const float* sel    = (const float*)d_in[1];   // frame_selection [64, 2, 64]
    const float* ratios = (const float*)d_in[2];   // split_ratios    [64]
    float* out = (float*)d_out;                    // [3, 2048, 2048] fp32

    k_tree<<<16, 512>>>(sel, ratios);
    k_pre<<<(NPX * NPY) / 256, 256>>>();

    dim3 block(32, 8);
    dim3 grid(NPX, NPY / 8);
    k_render<<<grid, block>>>(colors, out);
}

// round 7
// speedup vs baseline: 1.1486x; 1.1486x over previous
#include <cuda_runtime.h>
#include <math.h>

#define HH 2048
#define WW 2048
#define NF 64
#define MAXD 12
#define NSLOT 8191            // heap-ordered tree, depths 0..12
#define PXW 32                // patch width  (warp x-span)
#define PXH 4                 // patch height (rows per thread)
#define NPX (WW / PXW)        // 64
#define NPY (HH / PXH)        // 512

// Explicit tree, heap order. Node j:
//   bit31=1 -> leaf; low 6 bits = frame color index
//   bit31=0 -> interior; bit30 = axis (1=vertical/x), low 16 bits = absolute split coord
__device__ int g_tree[NSLOT];

// ---------------------------------------------------------------------------
// Kernel 1: build explicit tree. Thread j walks root -> heap slot j with a
// BRANCHLESS fixed-form loop (selects, no divergent if/else) so the warp
// never replays. Argmax: 4 threads/row, float4 loads, 2-shfl merge.
// ---------------------------------------------------------------------------
__global__ __launch_bounds__(512) void k_tree(
    const float* __restrict__ sel,
    const float* __restrict__ ratios)
{
    __shared__ float s_ratio[NF];
    __shared__ int   s_left[NF], s_right[NF];

    const int tid = threadIdx.x;

    // ---- argmax: row = tid>>2 (0..127), sub = tid&3 covers 16 elements ----
    {
        const int row   = tid >> 2;
        const int sub   = tid & 3;
        const int frame = row >> 1;
        const int side  = row & 1;
        const float4* p = (const float4*)(sel + frame * 2 * NF + side * NF + sub * 16);

        float4 a = p[0], b = p[1], c = p[2], d = p[3];
        float vals[16] = {a.x,a.y,a.z,a.w, b.x,b.y,b.z,b.w,
                          c.x,c.y,c.z,c.w, d.x,d.y,d.z,d.w};
        float best = vals[0];
        int   bi   = sub * 16;
        #pragma unroll
        for (int k = 1; k < 16; k++)
            if (vals[k] > best) { best = vals[k]; bi = sub * 16 + k; }

        #pragma unroll
        for (int off = 1; off <= 2; off <<= 1) {
            float ov = __shfl_xor_sync(0xffffffffu, best, off);
            int   oi = __shfl_xor_sync(0xffffffffu, bi,   off);
            if (ov > best || (ov == best && oi < bi)) { best = ov; bi = oi; }
        }
        if (sub == 0) { if (side == 0) s_left[frame] = bi; else s_right[frame] = bi; }
    }
    if (tid < NF) s_ratio[tid] = ratios[tid];
    __syncthreads();

    const int j = blockIdx.x * 512 + tid;
    if (j >= NSLOT) return;

    const int depth = 31 - __clz(j + 1);        // 0..12
    int idx = 0, x0 = 0, y0 = 0, w = WW, h = HH;
    bool dead = false;                          // an ancestor was a leaf

    for (int k = depth - 1; k >= 0; k--) {
        bool leaf = (w < 2) | (h < 2);
        dead = dead | leaf;
        int  bit  = ((j + 1) >> k) & 1;         // 0=left, 1=right
        int  vert = idx & 1;
        float rt  = s_ratio[idx];
        int  dim  = vert ? w : h;
        int  cut  = max(1, (int)floorf((float)dim * rt));
        int  ndim = bit ? dim - cut : cut;
        int  oadd = bit ? cut : 0;
        int  nidx = bit ? s_right[idx] : s_left[idx];
        if (!dead) {                            // small body -> predicated
            if (vert) { x0 += oadd; w = ndim; }
            else      { y0 += oadd; h = ndim; }
            idx = nidx;
        }
    }
    if (dead) return;                           // unreachable slot

    if (depth == MAXD || w < 2 || h < 2) {
        g_tree[j] = (int)0x80000000 | idx;
    } else {
        float rt = s_ratio[idx];
        if (idx & 1) g_tree[j] = (1 << 30) | (x0 + max(1, (int)floorf((float)w * rt)));
        else         g_tree[j] =             (y0 + max(1, (int)floorf((float)h * rt)));
    }
}

// ---------------------------------------------------------------------------
// Kernel 2: render. Warp = one 32x4 patch; thread owns 4 rows at fixed x.
// The patch prefix is computed inline, warp-redundantly (all lanes identical
// -> uniform control flow, no divergence, no separate kernel). Then per-lane
// descent with y-run reuse; horizontal boundaries are warp-convergent.
// ---------------------------------------------------------------------------
__global__ __launch_bounds__(256) void k_render(
    const float* __restrict__ colors,
    float* __restrict__ out)
{
    __shared__ float4 s_col[NF];
    const int t = threadIdx.y * 32 + threadIdx.x;
    if (t < NF)
        s_col[t] = make_float4(colors[3 * t], colors[3 * t + 1], colors[3 * t + 2], 0.f);
    __syncthreads();

    const int px    = blockIdx.x;                       // 0..63
    const int py    = blockIdx.y * 8 + threadIdx.y;     // 0..511
    const int tx0   = px * PXW;
    const int ybase = py * PXH;

    // ---- warp-uniform prefix walk (identical on every lane) ----
    int pcur = 0, preach = HH;
    {
        int v = __ldg(&g_tree[0]);
        while (v >= 0) {
            int s = v & 0xFFFF;
            if (v & (1 << 30)) {                        // vertical split
                if      (tx0 + PXW <= s) pcur = 2 * pcur + 1;
                else if (tx0 >= s)       pcur = 2 * pcur + 2;
                else break;
            } else {                                    // horizontal split
                if      (ybase + PXH <= s) { preach = min(preach, s); pcur = 2 * pcur + 1; }
                else if (ybase >= s)         pcur = 2 * pcur + 2;
                else break;
            }
            v = __ldg(&g_tree[pcur]);
        }
    }

    const int x    = tx0 + threadIdx.x;
    const int base = ybase * WW + x;

    float4 col = make_float4(0.f, 0.f, 0.f, 0.f);
    int reachy = -1;

    #pragma unroll
    for (int q = 0; q < PXH; q++) {
        const int y = ybase + q;
        if (y >= reachy) {
            int cur = pcur, ry = preach;
            int v = __ldg(&g_tree[cur]);
            while (v >= 0) {
                int s = v & 0xFFFF;
                bool vert = (v & (1 << 30)) != 0;
                int coord = vert ? x : y;
                if (coord >= s) cur = 2 * cur + 2;
                else { if (!vert) ry = min(ry, s); cur = 2 * cur + 1; }
                v = __ldg(&g_tree[cur]);
            }
            col = s_col[v & 63];
            reachy = ry;
        }
        out[base + q * WW]               = col.x;
        out[HH * WW + base + q * WW]     = col.y;
        out[2 * HH * WW + base + q * WW] = col.z;
    }
}

extern "C" void kernel_launch(void* const* d_in, const int* in_sizes, int n_in,
                              void* d_out, int out_size) {
    const float* colors = (const float*)d_in[0];   // frame_colors    [64, 3]
    const float* sel    = (const float*)d_in[1];   // frame_selection [64, 2, 64]
    const float* ratios = (const float*)d_in[2];   // split_ratios    [64]
    float* out = (float*)d_out;                    // [3, 2048, 2048] fp32

    k_tree<<<16, 512>>>(sel, ratios);

    dim3 block(32, 8);
    dim3 grid(NPX, NPY / 8);                       // 64 x 64
    k_render<<<grid, block>>>(colors, out);
}

// round 8
// speedup vs baseline: 1.1581x; 1.0083x over previous
#include <cuda_runtime.h>
#include <math.h>

#define HH 2048
#define WW 2048
#define NF 64
#define MAXD 12
#define NSLOT 8191            // heap-ordered tree, depths 0..12
#define PXW 32                // patch width  (warp x-span)
#define PXH 4                 // patch height (rows per thread)
#define NPX (WW / PXW)        // 64
#define NPY (HH / PXH)        // 512

// Node encoding (self-looping leaves, branchless descent):
//   bits [11:0]  split coordinate (interior) or 4095 sentinel (leaf)
//   bits [24:12] child base index (interior: 2j+1; leaf: j -> self-loop)
//   bit  [25]    axis (1 = vertical/x split)
//   bits [31:26] color index (leaf only)
__device__ int g_tree[NSLOT];

// ---------------------------------------------------------------------------
// Kernel 1: build explicit tree. Thread j walks root -> heap slot j
// (branchless walk). Argmax: 4 threads/row, float4 loads, 2-shfl merge.
// ---------------------------------------------------------------------------
__global__ __launch_bounds__(512) void k_tree(
    const float* __restrict__ sel,
    const float* __restrict__ ratios)
{
    __shared__ float s_ratio[NF];
    __shared__ int   s_left[NF], s_right[NF];

    const int tid = threadIdx.x;

    {   // ---- argmax: row = tid>>2 (0..127), sub = tid&3 covers 16 elems ----
        const int row   = tid >> 2;
        const int sub   = tid & 3;
        const int frame = row >> 1;
        const int side  = row & 1;
        const float4* p = (const float4*)(sel + frame * 2 * NF + side * NF + sub * 16);

        float4 a = p[0], b = p[1], c = p[2], d = p[3];
        float vals[16] = {a.x,a.y,a.z,a.w, b.x,b.y,b.z,b.w,
                          c.x,c.y,c.z,c.w, d.x,d.y,d.z,d.w};
        float best = vals[0];
        int   bi   = sub * 16;
        #pragma unroll
        for (int k = 1; k < 16; k++)
            if (vals[k] > best) { best = vals[k]; bi = sub * 16 + k; }

        #pragma unroll
        for (int off = 1; off <= 2; off <<= 1) {
            float ov = __shfl_xor_sync(0xffffffffu, best, off);
            int   oi = __shfl_xor_sync(0xffffffffu, bi,   off);
            if (ov > best || (ov == best && oi < bi)) { best = ov; bi = oi; }
        }
        if (sub == 0) { if (side == 0) s_left[frame] = bi; else s_right[frame] = bi; }
    }
    if (tid < NF) s_ratio[tid] = ratios[tid];
    __syncthreads();

    const int j = blockIdx.x * 512 + tid;
    if (j >= NSLOT) return;

    const int depth = 31 - __clz(j + 1);        // 0..12
    int idx = 0, x0 = 0, y0 = 0, w = WW, h = HH;
    bool dead = false;

    for (int k = depth - 1; k >= 0; k--) {
        bool leaf = (w < 2) | (h < 2);
        dead = dead | leaf;
        int  bit  = ((j + 1) >> k) & 1;
        int  vert = idx & 1;
        float rt  = s_ratio[idx];
        int  dim  = vert ? w : h;
        int  cut  = max(1, (int)floorf((float)dim * rt));
        int  ndim = bit ? dim - cut : cut;
        int  oadd = bit ? cut : 0;
        int  nidx = bit ? s_right[idx] : s_left[idx];
        if (!dead) {
            if (vert) { x0 += oadd; w = ndim; }
            else      { y0 += oadd; h = ndim; }
            idx = nidx;
        }
    }
    if (dead) return;                           // unreachable slot (garbage ok)

    if (depth == MAXD || w < 2 || h < 2) {
        g_tree[j] = 4095 | (j << 12) | (idx << 26);             // leaf, self-loop
    } else {
        float rt = s_ratio[idx];
        int s;
        if (idx & 1) s = x0 + max(1, (int)floorf((float)w * rt));
        else         s = y0 + max(1, (int)floorf((float)h * rt));
        g_tree[j] = s | ((2 * j + 1) << 12) | ((idx & 1) << 25);
    }
}

// ---------------------------------------------------------------------------
// Kernel 2: render. Warp = 32x4 patch; thread owns 4 rows at fixed x.
// Warp-uniform prefix walk (branchy, uniform -> free) records depth pd;
// per-lane descent is BRANCHLESS with exactly MAXD-pd trips (self-looping
// leaves make overshoot harmless). Uniform fast path when the patch lies
// entirely inside one leaf.
// ---------------------------------------------------------------------------
__global__ __launch_bounds__(256) void k_render(
    const float* __restrict__ colors,
    float* __restrict__ out)
{
    __shared__ float4 s_col[NF];
    const int t = threadIdx.y * 32 + threadIdx.x;
    if (t < NF)
        s_col[t] = make_float4(colors[3 * t], colors[3 * t + 1], colors[3 * t + 2], 0.f);
    __syncthreads();

    const int tx0   = blockIdx.x * PXW;
    const int py    = blockIdx.y * 8 + threadIdx.y;     // 0..511
    const int ybase = py * PXH;
    const int x     = tx0 + threadIdx.x;
    const int base  = ybase * WW + x;

    // ---- warp-uniform prefix walk ----
    int pcur = 0, preach = HH, pd = 0;
    int pv = __ldg(&g_tree[0]);
    bool pleaf = false;
    while (true) {
        int s = pv & 0xFFF;
        if (s == 4095) { pleaf = true; break; }         // patch inside a leaf
        if (pv & (1 << 25)) {                           // vertical split
            if      (tx0 + PXW <= s) pcur = 2 * pcur + 1;
            else if (tx0 >= s)       pcur = 2 * pcur + 2;
            else break;
        } else {                                        // horizontal split
            if      (ybase + PXH <= s) { preach = min(preach, s); pcur = 2 * pcur + 1; }
            else if (ybase >= s)         pcur = 2 * pcur + 2;
            else break;
        }
        pd++;
        pv = __ldg(&g_tree[pcur]);
    }

    if (pleaf) {                                        // whole-patch fast path
        float4 col = s_col[(unsigned)pv >> 26];
        #pragma unroll
        for (int q = 0; q < PXH; q++) {
            out[base + q * WW]               = col.x;
            out[HH * WW + base + q * WW]     = col.y;
            out[2 * HH * WW + base + q * WW] = col.z;
        }
        return;
    }

    const int TR = MAXD - pd;                           // uniform trip count

    float4 col = make_float4(0.f, 0.f, 0.f, 0.f);
    int reachy = -1;

    #pragma unroll
    for (int q = 0; q < PXH; q++) {
        const int y = ybase + q;
        if (y >= reachy) {                              // warp-convergent trigger
            int cur = pcur, ry = preach;
            int v = pv;
            #pragma unroll 4
            for (int it = 0; it < TR; it++) {           // branchless fixed trips
                int  s     = v & 0xFFF;
                bool vert  = (v & (1 << 25)) != 0;
                int  coord = vert ? x : y;
                bool go    = coord >= s;
                if (!vert && !go) ry = min(ry, s);
                cur = ((v >> 12) & 0x1FFF) + (go ? 1 : 0);
                v = __ldg(&g_tree[cur]);
            }
            col = s_col[(unsigned)v >> 26];
            reachy = ry;
        }
        out[base + q * WW]               = col.x;
        out[HH * WW + base + q * WW]     = col.y;
        out[2 * HH * WW + base + q * WW] = col.z;
    }
}

extern "C" void kernel_launch(void* const* d_in, const int* in_sizes, int n_in,
                              void* d_out, int out_size) {
    const float* colors = (const float*)d_in[0];   // frame_colors    [64, 3]
    const float* sel    = (const float*)d_in[1];   // frame_selection [64, 2, 64]
    const float* ratios = (const float*)d_in[2];   // split_ratios    [64]
    float* out = (float*)d_out;                    // [3, 2048, 2048] fp32

    k_tree<<<16, 512>>>(sel, ratios);

    dim3 block(32, 8);
    dim3 grid(NPX, NPY / 8);                       // 64 x 64
    k_render<<<grid, block>>>(colors, out);
}